// round 1
// baseline (speedup 1.0000x reference)
#include <cuda_runtime.h>

#define NB 2048
#define NT 128
#define NS 256
#define NH 64
#define NE 32
#define NV 29
#define G4 256        // 4*H
#define ENC_PAD 65    // conflict-free stride for [s][k] and [k-strided] access

// Precomputed: G[v][j] = b_ih[j] + b_hh[j] + emb_table[v] . W_ih[j, 0:32]
__device__ float g_table_dev[NV * G4];

__global__ void build_g_table(const float* __restrict__ emb,
                              const float* __restrict__ W_ih,
                              const float* __restrict__ b_ih,
                              const float* __restrict__ b_hh) {
    __shared__ float es[NE];
    int v = blockIdx.x, j = threadIdx.x;
    if (j < NE) es[j] = emb[v * NE + j];
    __syncthreads();
    float acc = b_ih[j] + b_hh[j];
#pragma unroll
    for (int e = 0; e < NE; e++) acc += es[e] * W_ih[j * (NE + NH) + e];
    g_table_dev[v * G4 + j] = acc;
}

// ---- shared memory layout (floats) ----
constexpr int OFF_ENC  = 0;                         // 256*65 = 16640
constexpr int OFF_GTAB = OFF_ENC + NS * ENC_PAD;    // 29*256 = 7424
constexpr int OFF_FCW  = OFF_GTAB + NV * G4;        // 29*129 = 3741 -> pad 3744
constexpr int OFF_ATTN = OFF_FCW + 3744;            // 256
constexpr int OFF_PSM  = OFF_ATTN + NS;             // 4*64
constexpr int OFF_LSM  = OFF_PSM + 4 * NH;          // 8*32
constexpr int OFF_RED  = OFF_LSM + 8 * 32;          // 16
constexpr int OFF_HSM  = OFF_RED + 16;              // 64 (float4-aligned)
constexpr int OFF_CTX  = OFF_HSM + NH;              // 64
constexpr int OFF_GSM  = OFF_CTX + NH;              // 256
constexpr int OFF_FCB  = OFF_GSM + G4;              // 32
constexpr int OFF_Y    = OFF_FCB + 32;              // 128 ints
constexpr int SMEM_FLOATS = OFF_Y + NT;
constexpr int SMEM_BYTES  = SMEM_FLOATS * 4;

__device__ __forceinline__ float sigmoid_fast(float x) {
    return __fdividef(1.f, 1.f + __expf(-x));
}
__device__ __forceinline__ float tanh_fast(float x) {
    float e = __expf(2.f * x);
    return 1.f - __fdividef(2.f, e + 1.f);
}

__global__ void __launch_bounds__(256, 1)
decoder_main(const int* __restrict__ y_g, const float* __restrict__ h0,
             const float* __restrict__ c0, const float* __restrict__ enc_g,
             const float* __restrict__ W_ih, const float* __restrict__ W_hh,
             const float* __restrict__ fc_W, const float* __restrict__ fc_b,
             float* __restrict__ out) {
    extern __shared__ float sm[];
    float* enc  = sm + OFF_ENC;
    float* gtab = sm + OFF_GTAB;
    float* fcw  = sm + OFF_FCW;
    float* attn = sm + OFF_ATTN;
    float* psm  = sm + OFF_PSM;
    float* lsm  = sm + OFF_LSM;
    float* redm = sm + OFF_RED;      // 8 for max
    float* reds = sm + OFF_RED + 8;  // 8 for sum
    float* hsm  = sm + OFF_HSM;
    float* ctx  = sm + OFF_CTX;
    float* gsm  = sm + OFF_GSM;
    float* fcb  = sm + OFF_FCB;
    int*   ysm  = (int*)(sm + OFF_Y);

    const int tid  = threadIdx.x;
    const int b    = blockIdx.x;
    const int lane = tid & 31;
    const int wid  = tid >> 5;

    // ---------- one-time loads ----------
    const float* encb = enc_g + (size_t)b * NS * NH;
    for (int i = tid; i < NS * NH; i += 256) {
        int s = i >> 6, k = i & 63;
        enc[s * ENC_PAD + k] = encb[i];
    }
    for (int i = tid; i < NV * G4; i += 256) gtab[i] = g_table_dev[i];
    for (int i = tid; i < NV * 2 * NH; i += 256) {
        int v = i >> 7, d = i & 127;
        fcw[v * 129 + d] = fc_W[i];
    }
    if (tid < NV) fcb[tid] = fc_b[tid];
    if (tid < NT) ysm[tid] = y_g[b * NT + tid];
    if (tid < NH) hsm[tid] = h0[b * NH + tid];
    float c_reg = (tid < NH) ? c0[b * NH + tid] : 0.f;

    // gate-row weights in registers: thread j owns W_ih[j, 32:96] and W_hh[j, :]
    float wc[NH], wh[NH];
#pragma unroll
    for (int k = 0; k < NH; k++) {
        wc[k] = W_ih[tid * (NE + NH) + NE + k];
        wh[k] = W_hh[tid * NH + k];
    }
    __syncthreads();

    float* outb = out + (size_t)b * NT * NV;
    const float4* h4 = (const float4*)hsm;
    const float4* c4 = (const float4*)ctx;

    for (int t = 0; t < NT; t++) {
        // ---- 1. scores: thread == s ----
        const float* er = enc + tid * ENC_PAD;
        float a0 = 0.f, a1 = 0.f, a2 = 0.f, a3 = 0.f;
#pragma unroll
        for (int i = 0; i < 16; i++) {
            float4 hv = h4[i];
            a0 += er[4 * i + 0] * hv.x;
            a1 += er[4 * i + 1] * hv.y;
            a2 += er[4 * i + 2] * hv.z;
            a3 += er[4 * i + 3] * hv.w;
        }
        float sc = (a0 + a1) + (a2 + a3);

        // ---- 2. softmax over 256 ----
        float m = sc;
#pragma unroll
        for (int o = 16; o; o >>= 1) m = fmaxf(m, __shfl_xor_sync(0xffffffffu, m, o));
        if (lane == 0) redm[wid] = m;
        __syncthreads();
        m = redm[0];
#pragma unroll
        for (int w = 1; w < 8; w++) m = fmaxf(m, redm[w]);
        float e = __expf(sc - m);
        float ssum = e;
#pragma unroll
        for (int o = 16; o; o >>= 1) ssum += __shfl_xor_sync(0xffffffffu, ssum, o);
        if (lane == 0) reds[wid] = ssum;
        __syncthreads();
        float tot = reds[0];
#pragma unroll
        for (int w = 1; w < 8; w++) tot += reds[w];
        attn[tid] = __fdividef(e, tot);
        __syncthreads();

        // ---- 3. context: thread = (chunk, k) ----
        {
            int k = tid & 63, chunk = tid >> 6;
            const float4* a4 = (const float4*)(attn + chunk * 64);
            const float* ec = enc + (chunk * 64) * ENC_PAD + k;
            float p0 = 0.f, p1 = 0.f, p2 = 0.f, p3 = 0.f;
#pragma unroll
            for (int i = 0; i < 16; i++) {
                float4 av = a4[i];
                p0 += av.x * ec[(4 * i + 0) * ENC_PAD];
                p1 += av.y * ec[(4 * i + 1) * ENC_PAD];
                p2 += av.z * ec[(4 * i + 2) * ENC_PAD];
                p3 += av.w * ec[(4 * i + 3) * ENC_PAD];
            }
            psm[chunk * NH + k] = (p0 + p1) + (p2 + p3);
        }
        __syncthreads();
        if (tid < NH)
            ctx[tid] = psm[tid] + psm[NH + tid] + psm[2 * NH + tid] + psm[3 * NH + tid];
        __syncthreads();

        // ---- 4. gates: thread == gate row j ----
        {
            int yt = ysm[t];
            float g0 = gtab[yt * G4 + tid], g1 = 0.f, g2 = 0.f, g3 = 0.f;
#pragma unroll
            for (int i = 0; i < 16; i++) {
                float4 cv = c4[i];
                g0 += wc[4 * i + 0] * cv.x;
                g1 += wc[4 * i + 1] * cv.y;
                g2 += wc[4 * i + 2] * cv.z;
                g3 += wc[4 * i + 3] * cv.w;
            }
#pragma unroll
            for (int i = 0; i < 16; i++) {
                float4 hv = h4[i];
                g0 += wh[4 * i + 0] * hv.x;
                g1 += wh[4 * i + 1] * hv.y;
                g2 += wh[4 * i + 2] * hv.z;
                g3 += wh[4 * i + 3] * hv.w;
            }
            gsm[tid] = (g0 + g1) + (g2 + g3);
        }
        __syncthreads();

        // ---- 5. LSTM cell: threads 0..63, c kept in register ----
        if (tid < NH) {
            float gi = gsm[tid];
            float gf = gsm[NH + tid];
            float gg = gsm[2 * NH + tid];
            float go = gsm[3 * NH + tid];
            c_reg = sigmoid_fast(gf) * c_reg + sigmoid_fast(gi) * tanh_fast(gg);
            hsm[tid] = sigmoid_fast(go) * tanh_fast(c_reg);
        }
        __syncthreads();

        // ---- 6. logits: thread = (p = tid>>5, v = tid&31), 16 dims each ----
        {
            int v = tid & 31, p = tid >> 5;
            float lp = 0.f;
            if (v < NV) {
                const float* fr = fcw + v * 129 + p * 16;
                const float* cb = (p < 4) ? (hsm + p * 16) : (ctx + (p - 4) * 16);
#pragma unroll
                for (int i = 0; i < 16; i++) lp += fr[i] * cb[i];
            }
            lsm[p * 32 + v] = lp;
        }
        __syncthreads();
        if (tid < NV) {
            float l = fcb[tid];
#pragma unroll
            for (int p2 = 0; p2 < 8; p2++) l += lsm[p2 * 32 + tid];
            outb[t * NV + tid] = l;
        }
        // no trailing barrier needed: every buffer rewritten next step has
        // intervening __syncthreads() before its next producer.
    }
}

extern "C" void kernel_launch(void* const* d_in, const int* in_sizes, int n_in,
                              void* d_out, int out_size) {
    const int*   y    = (const int*)d_in[0];
    const float* h0   = (const float*)d_in[1];
    const float* c0   = (const float*)d_in[2];
    const float* enc  = (const float*)d_in[3];
    const float* emb  = (const float*)d_in[4];
    const float* W_ih = (const float*)d_in[5];
    const float* W_hh = (const float*)d_in[6];
    const float* b_ih = (const float*)d_in[7];
    const float* b_hh = (const float*)d_in[8];
    const float* fc_W = (const float*)d_in[9];
    const float* fc_b = (const float*)d_in[10];
    float* out = (float*)d_out;

    build_g_table<<<NV, 256>>>(emb, W_ih, b_ih, b_hh);

    cudaFuncSetAttribute(decoder_main,
                         cudaFuncAttributeMaxDynamicSharedMemorySize, SMEM_BYTES);
    decoder_main<<<NB, 256, SMEM_BYTES>>>(y, h0, c0, enc, W_ih, W_hh,
                                          fc_W, fc_b, out);
}

// round 4
// speedup vs baseline: 1.2150x; 1.2150x over previous
#include <cuda_runtime.h>

#define NB 2048
#define NT 128
#define NS 256
#define NH 64
#define NE 32
#define NV 29
#define G4 256        // 4*H
#define ENC_PAD 68    // 16B-aligned rows AND conflict-free for both passes
#define ROWS 2        // batch rows per CTA

// Precomputed: G[v][j] = b_ih[j] + b_hh[j] + emb_table[v] . W_ih[j, 0:32]
__device__ float g_table_dev[NV * G4];

__global__ void build_g_table(const float* __restrict__ emb,
                              const float* __restrict__ W_ih,
                              const float* __restrict__ b_ih,
                              const float* __restrict__ b_hh) {
    __shared__ float es[NE];
    int v = blockIdx.x, j = threadIdx.x;
    if (j < NE) es[j] = emb[v * NE + j];
    __syncthreads();
    float acc = b_ih[j] + b_hh[j];
#pragma unroll
    for (int e = 0; e < NE; e++) acc += es[e] * W_ih[j * (NE + NH) + e];
    g_table_dev[v * G4 + j] = acc;
}

// ---- shared memory layout (floats) ----
constexpr int ENC_ROW_FLOATS = NS * ENC_PAD;            // 17408
constexpr int OFF_ENC  = 0;                             // 2*17408 = 34816
constexpr int OFF_GTAB = OFF_ENC + ROWS * ENC_ROW_FLOATS; // 7424
constexpr int OFF_FCW  = OFF_GTAB + NV * G4;            // 29*129 = 3741 -> pad 3744
constexpr int OFF_ATTN = OFF_FCW + 3744;                // 2*256 = 512
constexpr int OFF_PSM  = OFF_ATTN + ROWS * NS;          // 2*2*64 = 256
constexpr int OFF_HSM  = OFF_PSM + 256;                 // 2*64 = 128
constexpr int OFF_CTX  = OFF_HSM + ROWS * NH;           // 128
constexpr int OFF_GSM  = OFF_CTX + ROWS * NH;           // 2*256 = 512
constexpr int OFF_LSM  = OFF_GSM + ROWS * G4;           // 2*4*32 = 256
constexpr int OFF_RED  = OFF_LSM + 256;                 // 16
constexpr int OFF_FCB  = OFF_RED + 16;                  // 32
constexpr int OFF_Y    = OFF_FCB + 32;                  // 2*128 ints
constexpr int SMEM_FLOATS = OFF_Y + ROWS * NT;
constexpr int SMEM_BYTES  = SMEM_FLOATS * 4;            // ~192.5 KB

__device__ __forceinline__ float sigmoid_fast(float x) {
    return __fdividef(1.f, 1.f + __expf(-x));
}
__device__ __forceinline__ float tanh_fast(float x) {
    float e = __expf(2.f * x);
    return 1.f - __fdividef(2.f, e + 1.f);
}

__global__ void __launch_bounds__(256, 1)
decoder_main(const int* __restrict__ y_g, const float* __restrict__ h0,
             const float* __restrict__ c0, const float* __restrict__ enc_g,
             const float* __restrict__ W_ih, const float* __restrict__ W_hh,
             const float* __restrict__ fc_W, const float* __restrict__ fc_b,
             float* __restrict__ out) {
    extern __shared__ float sm[];
    float* enc0 = sm + OFF_ENC;                  // row 0
    float* enc1 = sm + OFF_ENC + ENC_ROW_FLOATS; // row 1
    float* gtab = sm + OFF_GTAB;
    float* fcw  = sm + OFF_FCW;
    float* attn = sm + OFF_ATTN;   // [row][256]
    float* psm  = sm + OFF_PSM;    // [row][chunk][64]
    float* hsm  = sm + OFF_HSM;    // [row][64]
    float* ctx  = sm + OFF_CTX;    // [row][64]
    float* gsm  = sm + OFF_GSM;    // [row][256]
    float* lsm  = sm + OFF_LSM;    // [row][4][32]
    float* reds = sm + OFF_RED;    // [row][8]
    float* fcb  = sm + OFF_FCB;
    int*   ysm  = (int*)(sm + OFF_Y); // [row][128]

    const int tid  = threadIdx.x;
    const int lane = tid & 31;
    const int wid  = tid >> 5;
    const int b0   = blockIdx.x * ROWS;

    // ---------- one-time loads ----------
#pragma unroll
    for (int r = 0; r < ROWS; r++) {
        const float* encb = enc_g + (size_t)(b0 + r) * NS * NH;
        float* er = sm + OFF_ENC + r * ENC_ROW_FLOATS;
        for (int i = tid; i < NS * NH; i += 256) {
            int s = i >> 6, k = i & 63;
            er[s * ENC_PAD + k] = encb[i];
        }
    }
    for (int i = tid; i < NV * G4; i += 256) gtab[i] = g_table_dev[i];
    for (int i = tid; i < NV * 2 * NH; i += 256) {
        int v = i >> 7, d = i & 127;
        fcw[v * 129 + d] = fc_W[i];
    }
    if (tid < NV) fcb[tid] = fc_b[tid];
    for (int i = tid; i < ROWS * NT; i += 256) {
        int r = i >> 7, t = i & 127;
        ysm[i] = y_g[(size_t)(b0 + r) * NT + t];
    }
    if (tid < ROWS * NH) {
        int r = tid >> 6, k = tid & 63;
        hsm[tid] = h0[(size_t)(b0 + r) * NH + k];
    }
    float c_reg = (tid < ROWS * NH)
                      ? c0[(size_t)(b0 + (tid >> 6)) * NH + (tid & 63)]
                      : 0.f;

    // gate-row weights: thread j owns W_ih[j, 32:96] and W_hh[j, :] (both rows reuse)
    float wc[NH], wh[NH];
#pragma unroll
    for (int k = 0; k < NH; k++) {
        wc[k] = W_ih[tid * (NE + NH) + NE + k];
        wh[k] = W_hh[tid * NH + k];
    }
    __syncthreads();

    const float4* h4_0 = (const float4*)hsm;
    const float4* h4_1 = (const float4*)(hsm + NH);
    const float4* c4_0 = (const float4*)ctx;
    const float4* c4_1 = (const float4*)(ctx + NH);

    for (int t = 0; t < NT; t++) {
        // ---- 1. scores (thread == s, both rows), vectorized LDS.128 ----
        const float4* e40 = (const float4*)(enc0 + tid * ENC_PAD);
        const float4* e41 = (const float4*)(enc1 + tid * ENC_PAD);
        float a00 = 0.f, a01 = 0.f, a02 = 0.f, a03 = 0.f;
        float a10 = 0.f, a11 = 0.f, a12 = 0.f, a13 = 0.f;
#pragma unroll
        for (int i = 0; i < 16; i++) {
            float4 ev0 = e40[i], ev1 = e41[i];
            float4 hv0 = h4_0[i], hv1 = h4_1[i];
            a00 += ev0.x * hv0.x; a01 += ev0.y * hv0.y;
            a02 += ev0.z * hv0.z; a03 += ev0.w * hv0.w;
            a10 += ev1.x * hv1.x; a11 += ev1.y * hv1.y;
            a12 += ev1.z * hv1.z; a13 += ev1.w * hv1.w;
        }
        float sc0 = (a00 + a01) + (a02 + a03);
        float sc1 = (a10 + a11) + (a12 + a13);

        // ---- 2. softmax (no max-subtraction: |score| bounded, exp safe) ----
        float e0 = __expf(sc0), e1 = __expf(sc1);
        float s0 = e0, s1 = e1;
#pragma unroll
        for (int o = 16; o; o >>= 1) {
            s0 += __shfl_xor_sync(0xffffffffu, s0, o);
            s1 += __shfl_xor_sync(0xffffffffu, s1, o);
        }
        if (lane == 0) { reds[wid] = s0; reds[8 + wid] = s1; }
        __syncthreads();
        float tot0 = reds[0], tot1 = reds[8];
#pragma unroll
        for (int w = 1; w < 8; w++) { tot0 += reds[w]; tot1 += reds[8 + w]; }
        attn[tid]      = __fdividef(e0, tot0);
        attn[NS + tid] = __fdividef(e1, tot1);
        __syncthreads();

        // ---- 3. context partials: thread = (row, chunk in 2, k) ----
        {
            int k = tid & 63, chunk = (tid >> 6) & 1, row = tid >> 7;
            const float* encR = sm + OFF_ENC + row * ENC_ROW_FLOATS;
            const float*  ec  = encR + (chunk * 128) * ENC_PAD + k;
            const float4* a4  = (const float4*)(attn + row * NS + chunk * 128);
            float p0 = 0.f, p1 = 0.f, p2 = 0.f, p3 = 0.f;
#pragma unroll
            for (int i = 0; i < 32; i++) {
                float4 av = a4[i];
                p0 += av.x * ec[(4 * i + 0) * ENC_PAD];
                p1 += av.y * ec[(4 * i + 1) * ENC_PAD];
                p2 += av.z * ec[(4 * i + 2) * ENC_PAD];
                p3 += av.w * ec[(4 * i + 3) * ENC_PAD];
            }
            psm[row * 128 + chunk * 64 + k] = (p0 + p1) + (p2 + p3);
        }
        __syncthreads();
        if (tid < ROWS * NH) {
            int r = tid >> 6, k = tid & 63;
            ctx[tid] = psm[r * 128 + k] + psm[r * 128 + 64 + k];
        }
        __syncthreads();

        // ---- 4. gates: thread == gate row j, both rows ----
        {
            int yt0 = ysm[t], yt1 = ysm[NT + t];
            float g00 = gtab[yt0 * G4 + tid], g01 = 0.f, g02 = 0.f, g03 = 0.f;
            float g10 = gtab[yt1 * G4 + tid], g11 = 0.f, g12 = 0.f, g13 = 0.f;
#pragma unroll
            for (int i = 0; i < 16; i++) {
                float4 cv0 = c4_0[i], cv1 = c4_1[i];
                g00 += wc[4 * i + 0] * cv0.x; g01 += wc[4 * i + 1] * cv0.y;
                g02 += wc[4 * i + 2] * cv0.z; g03 += wc[4 * i + 3] * cv0.w;
                g10 += wc[4 * i + 0] * cv1.x; g11 += wc[4 * i + 1] * cv1.y;
                g12 += wc[4 * i + 2] * cv1.z; g13 += wc[4 * i + 3] * cv1.w;
            }
#pragma unroll
            for (int i = 0; i < 16; i++) {
                float4 hv0 = h4_0[i], hv1 = h4_1[i];
                g00 += wh[4 * i + 0] * hv0.x; g01 += wh[4 * i + 1] * hv0.y;
                g02 += wh[4 * i + 2] * hv0.z; g03 += wh[4 * i + 3] * hv0.w;
                g10 += wh[4 * i + 0] * hv1.x; g11 += wh[4 * i + 1] * hv1.y;
                g12 += wh[4 * i + 2] * hv1.z; g13 += wh[4 * i + 3] * hv1.w;
            }
            gsm[tid]      = (g00 + g01) + (g02 + g03);
            gsm[G4 + tid] = (g10 + g11) + (g12 + g13);
        }
        __syncthreads();

        // ---- 5. LSTM cell: threads 0..127 (row = tid>>6, k = tid&63) ----
        if (tid < ROWS * NH) {
            int r = tid >> 6, k = tid & 63;
            const float* g = gsm + r * G4;
            float gi = g[k], gf = g[NH + k], gg = g[2 * NH + k], go = g[3 * NH + k];
            c_reg = sigmoid_fast(gf) * c_reg + sigmoid_fast(gi) * tanh_fast(gg);
            hsm[tid] = sigmoid_fast(go) * tanh_fast(c_reg);
        }
        __syncthreads();

        // ---- 6. logits partials: thread = (row, p in 4, v in 32), 32 dims each ----
        {
            int v = tid & 31, p = (tid >> 5) & 3, r = tid >> 7;
            float lp = 0.f;
            if (v < NV) {
                const float* fr = fcw + v * 129 + p * 32;
                const float* cb = (p < 2) ? (hsm + r * NH + p * 32)
                                          : (ctx + r * NH + (p - 2) * 32);
#pragma unroll
                for (int i = 0; i < 32; i++) lp += fr[i] * cb[i];
            }
            lsm[r * 128 + p * 32 + v] = lp;
        }
        __syncthreads();
        if (tid < 64) {
            int r = tid >> 5, v = tid & 31;
            if (v < NV) {
                float l = fcb[v];
#pragma unroll
                for (int p2 = 0; p2 < 4; p2++) l += lsm[r * 128 + p2 * 32 + v];
                out[((size_t)(b0 + r) * NT + t) * NV + v] = l;
            }
        }
        // no trailing barrier: every smem buffer touched above has intervening
        // __syncthreads() before its next producer in the following iteration.
    }
}

extern "C" void kernel_launch(void* const* d_in, const int* in_sizes, int n_in,
                              void* d_out, int out_size) {
    const int*   y    = (const int*)d_in[0];
    const float* h0   = (const float*)d_in[1];
    const float* c0   = (const float*)d_in[2];
    const float* enc  = (const float*)d_in[3];
    const float* emb  = (const float*)d_in[4];
    const float* W_ih = (const float*)d_in[5];
    const float* W_hh = (const float*)d_in[6];
    const float* b_ih = (const float*)d_in[7];
    const float* b_hh = (const float*)d_in[8];
    const float* fc_W = (const float*)d_in[9];
    const float* fc_b = (const float*)d_in[10];
    float* out = (float*)d_out;

    build_g_table<<<NV, 256>>>(emb, W_ih, b_ih, b_hh);

    cudaFuncSetAttribute(decoder_main,
                         cudaFuncAttributeMaxDynamicSharedMemorySize, SMEM_BYTES);
    decoder_main<<<NB / ROWS, 256, SMEM_BYTES>>>(y, h0, c0, enc, W_ih, W_hh,
                                                 fc_W, fc_b, out);
}